// round 3
// baseline (speedup 1.0000x reference)
#include <cuda_runtime.h>
#include <math_constants.h>

#define HH 224
#define WW 224
#define HWP (HH * WW)      // 50176
#define BB 64
#define RBLK 16            // reduce blocks per batch

// Per-(batch, block) partial min/max. Plain stores -> no init kernel, no
// atomics; deterministic across graph replays.
__device__ float g_pmax[BB][RBLK];
__device__ float g_pmin[BB][RBLK];

__global__ void __launch_bounds__(256)
reduce_kernel(const float* __restrict__ depth, const float* __restrict__ obj) {
    const int b = blockIdx.y;
    const float4* dp = reinterpret_cast<const float4*>(depth + (size_t)b * HWP);
    const float4* op = reinterpret_cast<const float4*>(obj + (size_t)b * HWP);
    float mx = -CUDART_INF_F, mn = CUDART_INF_F;
    const int n4 = HWP / 4;  // 12544
    for (int i = blockIdx.x * blockDim.x + threadIdx.x; i < n4;
         i += RBLK * 256) {
        float4 d = dp[i];
        float4 o = op[i];
        float p0 = d.x * o.x, p1 = d.y * o.y, p2 = d.z * o.z, p3 = d.w * o.w;
        mx = fmaxf(mx, fmaxf(fmaxf(p0, p1), fmaxf(p2, p3)));
        mn = fminf(mn, fminf(fminf(p0, p1), fminf(p2, p3)));
    }
#pragma unroll
    for (int off = 16; off; off >>= 1) {
        mx = fmaxf(mx, __shfl_xor_sync(0xffffffffu, mx, off));
        mn = fminf(mn, __shfl_xor_sync(0xffffffffu, mn, off));
    }
    __shared__ float smx[8], smn[8];
    int w = threadIdx.x >> 5, l = threadIdx.x & 31;
    if (l == 0) { smx[w] = mx; smn[w] = mn; }
    __syncthreads();
    if (threadIdx.x == 0) {
#pragma unroll
        for (int i = 1; i < 8; i++) {
            mx = fmaxf(mx, smx[i]);
            mn = fminf(mn, smn[i]);
        }
        g_pmax[b][blockIdx.x] = mx;
        g_pmin[b][blockIdx.x] = mn;
    }
}

// 128 threads/block, 8 consecutive pixels (2 float4) per thread.
// 128*8 = 1024 px/block, 49 blocks per batch (49*1024 = 50176 = HW exactly).
// 8 divides 224, so each thread's pixels stay in one image row.
__global__ void __launch_bounds__(128)
main_kernel(const float* __restrict__ depth, const float* __restrict__ obj,
            const float* __restrict__ gaze, const long long* __restrict__ hp,
            float* __restrict__ out) {
    const int b  = blockIdx.x / 49;
    const int lb = blockIdx.x % 49;

    __shared__ float s_pd, s_fr, s_hp0f, s_hp1f, s_gx, s_gy, s_rn2;
    if (threadIdx.x < 32) {
        float mx = (threadIdx.x < RBLK) ? g_pmax[b][threadIdx.x] : -CUDART_INF_F;
        float mn = (threadIdx.x < RBLK) ? g_pmin[b][threadIdx.x] :  CUDART_INF_F;
#pragma unroll
        for (int off = 8; off; off >>= 1) {
            mx = fmaxf(mx, __shfl_xor_sync(0xffffffffu, mx, off));
            mn = fminf(mn, __shfl_xor_sync(0xffffffffu, mn, off));
        }
        if (threadIdx.x == 0) {
            int hp0 = (int)hp[2 * b];
            int hp1 = (int)hp[2 * b + 1];
            size_t hidx = (size_t)b * HWP + (size_t)hp0 * WW + hp1;
            float hd = depth[hidx] * obj[hidx];
            float gx = gaze[3 * b], gy = gaze[3 * b + 1], gz = gaze[3 * b + 2];
            s_pd = hd + gz * 224.0f;
            s_fr = (mx - mn) / 24.0f;
            s_hp0f = (float)hp0;
            s_hp1f = (float)hp1;
            s_gx = gx;
            s_gy = gy;
            s_rn2 = gx * gx + gy * gy;
        }
    }
    __syncthreads();

    const int t   = lb * 128 + threadIdx.x;   // 0..6271
    const int pix = t * 8;
    const int h   = pix / WW;
    const int w0  = pix % WW;

    const float* dbase = depth + (size_t)b * HWP + pix;
    const float* obase_in = obj + (size_t)b * HWP + pix;
    const float4 d4a = *reinterpret_cast<const float4*>(dbase);
    const float4 d4b = *reinterpret_cast<const float4*>(dbase + 4);
    const float4 o4a = *reinterpret_cast<const float4*>(obase_in);
    const float4 o4b = *reinterpret_cast<const float4*>(obase_in + 4);

    const float pd = s_pd, fr = s_fr;
    const float cf1 = fr, cf2 = 2.f * fr, cf3 = 3.f * fr;
    const float gx = s_gx, gy = s_gy, rn2 = s_rn2;
    const float a1   = (float)h - s_hp1f;
    const float a1gy = a1 * gy;
    const float a1sq = a1 * a1;
    const float a0b  = (float)w0 - s_hp0f;   // exact: small ints in fp32
    const float angscale = 12.0f / CUDART_PI_F;

    float dv[8] = {d4a.x * o4a.x, d4a.y * o4a.y, d4a.z * o4a.z, d4a.w * o4a.w,
                   d4b.x * o4b.x, d4b.y * o4b.y, d4b.z * o4b.z, d4b.w * o4b.w};

    // Cheap FMA-only cone gate for this thread's 8 pixels.
    // 0.93 < cos^2(pi/12)=0.93301: slightly loose so boundary fp noise can
    // only send extra pixels to the exact slow path, never skip a hit.
    bool any = false;
#pragma unroll
    for (int j = 0; j < 8; j++) {
        float a0  = a0b + (float)j;          // exact
        float dot = fmaf(a0, gx, a1gy);
        float tt  = fmaf(a0, a0, a1sq) * rn2;
        any = any || (dot > 0.f && dot * dot > 0.93f * tt);
    }

    float m[8] = {0.f, 0.f, 0.f, 0.f, 0.f, 0.f, 0.f, 0.f};
    if (any) {
        // Branch-free exact mask: out-of-cone -> negative -> 0; t==0 or
        // r>1 -> NaN -> fmaxf scrubs to 0 (== jnp.nan_to_num(maximum(...))).
#pragma unroll
        for (int j = 0; j < 8; j++) {
            float a0  = a0b + (float)j;
            float dot = fmaf(a0, gx, a1gy);
            float tt  = fmaf(a0, a0, a1sq) * rn2;
            float r   = dot * rsqrtf(tt);
            m[j] = fmaxf(fmaf(-angscale, acosf(r), 1.0f), 0.0f);
        }
    }

    float o0[8], o1[8], o2[8];
#pragma unroll
    for (int j = 0; j < 8; j++) {
        float d = dv[j];
        float e = fabsf(d - pd);             // |d - point_depth|
        float v = d * m[j];
        o0[j] = (e <= cf1) ? v : 0.f;
        o1[j] = (e <= cf2) ? v : 0.f;
        o2[j] = (e <= cf3) ? v : 0.f;
    }

    float* op0 = out + (size_t)b * 3 * HWP + pix;
    reinterpret_cast<float4*>(op0)[0]             = make_float4(o0[0], o0[1], o0[2], o0[3]);
    reinterpret_cast<float4*>(op0)[1]             = make_float4(o0[4], o0[5], o0[6], o0[7]);
    reinterpret_cast<float4*>(op0 + HWP)[0]       = make_float4(o1[0], o1[1], o1[2], o1[3]);
    reinterpret_cast<float4*>(op0 + HWP)[1]       = make_float4(o1[4], o1[5], o1[6], o1[7]);
    reinterpret_cast<float4*>(op0 + 2 * HWP)[0]   = make_float4(o2[0], o2[1], o2[2], o2[3]);
    reinterpret_cast<float4*>(op0 + 2 * HWP)[1]   = make_float4(o2[4], o2[5], o2[6], o2[7]);
}

extern "C" void kernel_launch(void* const* d_in, const int* in_sizes, int n_in,
                              void* d_out, int out_size) {
    const float* depth = (const float*)d_in[0];
    const float* obj   = (const float*)d_in[1];
    const float* gaze  = (const float*)d_in[2];
    const long long* hp = (const long long*)d_in[3];
    float* out = (float*)d_out;

    reduce_kernel<<<dim3(RBLK, BB), 256>>>(depth, obj);
    main_kernel<<<BB * 49, 128>>>(depth, obj, gaze, hp, out);
}

// round 4
// speedup vs baseline: 1.2557x; 1.2557x over previous
#include <cuda_runtime.h>
#include <math_constants.h>

#define HH 224
#define WW 224
#define HWP (HH * WW)      // 50176
#define BB 64
#define RBLK 16            // reduce blocks per batch

// Per-(batch, block) partial min/max. Plain stores -> no init kernel, no
// atomics; deterministic across graph replays.
__device__ float g_pmax[BB][RBLK];
__device__ float g_pmin[BB][RBLK];

__global__ void __launch_bounds__(256)
reduce_kernel(const float* __restrict__ depth, const float* __restrict__ obj) {
    const int b = blockIdx.y;
    const float4* dp = reinterpret_cast<const float4*>(depth + (size_t)b * HWP);
    const float4* op = reinterpret_cast<const float4*>(obj + (size_t)b * HWP);
    float mx = -CUDART_INF_F, mn = CUDART_INF_F;
    const int n4 = HWP / 4;  // 12544
    for (int i = blockIdx.x * blockDim.x + threadIdx.x; i < n4;
         i += RBLK * 256) {
        float4 d = dp[i];
        float4 o = op[i];
        float p0 = d.x * o.x, p1 = d.y * o.y, p2 = d.z * o.z, p3 = d.w * o.w;
        mx = fmaxf(mx, fmaxf(fmaxf(p0, p1), fmaxf(p2, p3)));
        mn = fminf(mn, fminf(fminf(p0, p1), fminf(p2, p3)));
    }
#pragma unroll
    for (int off = 16; off; off >>= 1) {
        mx = fmaxf(mx, __shfl_xor_sync(0xffffffffu, mx, off));
        mn = fminf(mn, __shfl_xor_sync(0xffffffffu, mn, off));
    }
    __shared__ float smx[8], smn[8];
    int w = threadIdx.x >> 5, l = threadIdx.x & 31;
    if (l == 0) { smx[w] = mx; smn[w] = mn; }
    __syncthreads();
    if (threadIdx.x == 0) {
#pragma unroll
        for (int i = 1; i < 8; i++) {
            mx = fmaxf(mx, smx[i]);
            mn = fminf(mn, smn[i]);
        }
        g_pmax[b][blockIdx.x] = mx;
        g_pmin[b][blockIdx.x] = mn;
    }
}

// 256 threads/block, one float4 (4 consecutive w-pixels, one row) per thread.
// 49 blocks per batch: 49*256*4 = 50176 = HW exactly.
__global__ void __launch_bounds__(256)
main_kernel(const float* __restrict__ depth, const float* __restrict__ obj,
            const float* __restrict__ gaze, const long long* __restrict__ hp,
            float* __restrict__ out) {
    const int b  = blockIdx.x / 49;
    const int lb = blockIdx.x % 49;

    __shared__ float s_pd, s_fr, s_hp0f, s_hp1f, s_gx, s_gy, s_rn2;
    if (threadIdx.x < 32) {
        float mx = (threadIdx.x < RBLK) ? g_pmax[b][threadIdx.x] : -CUDART_INF_F;
        float mn = (threadIdx.x < RBLK) ? g_pmin[b][threadIdx.x] :  CUDART_INF_F;
#pragma unroll
        for (int off = 8; off; off >>= 1) {
            mx = fmaxf(mx, __shfl_xor_sync(0xffffffffu, mx, off));
            mn = fminf(mn, __shfl_xor_sync(0xffffffffu, mn, off));
        }
        if (threadIdx.x == 0) {
            int hp0 = (int)hp[2 * b];
            int hp1 = (int)hp[2 * b + 1];
            size_t hidx = (size_t)b * HWP + (size_t)hp0 * WW + hp1;
            float hd = depth[hidx] * obj[hidx];
            float gx = gaze[3 * b], gy = gaze[3 * b + 1], gz = gaze[3 * b + 2];
            s_pd = hd + gz * 224.0f;
            s_fr = (mx - mn) / 24.0f;
            s_hp0f = (float)hp0;
            s_hp1f = (float)hp1;
            s_gx = gx;
            s_gy = gy;
            s_rn2 = gx * gx + gy * gy;
        }
    }
    __syncthreads();

    const int idx = lb * 256 + threadIdx.x;  // float4 index within image
    const int pix = idx * 4;
    const int h   = pix / WW;
    const int w0  = pix % WW;   // 4 consecutive pixels stay in one row

    const float4 d4 = *reinterpret_cast<const float4*>(depth + (size_t)b * HWP + pix);
    const float4 o4 = *reinterpret_cast<const float4*>(obj   + (size_t)b * HWP + pix);

    const float pd = s_pd, fr = s_fr;
    const float cf1 = fr, cf2 = 2.f * fr, cf3 = 3.f * fr;
    const float gx = s_gx, gy = s_gy, rn2 = s_rn2;
    const float a1   = (float)h - s_hp1f;
    const float a1gy = a1 * gy;
    const float a1sq = a1 * a1;
    const float a0b  = (float)w0 - s_hp0f;   // exact: small ints in fp32
    const float angscale = 12.0f / CUDART_PI_F;

    float dv[4] = {d4.x * o4.x, d4.y * o4.y, d4.z * o4.z, d4.w * o4.w};

    // Cheap FMA-only cone gate for this thread's 4 pixels.
    // 0.93 < cos^2(pi/12)=0.93301: slightly loose so fp noise only sends
    // extra pixels to the exact slow path, never skips a hit.
    bool any = false;
#pragma unroll
    for (int j = 0; j < 4; j++) {
        float a0  = a0b + (float)j;          // exact
        float dot = fmaf(a0, gx, a1gy);
        float tt  = fmaf(a0, a0, a1sq) * rn2;
        any = any || (dot > 0.f && dot * dot > 0.93f * tt);
    }

    float m[4] = {0.f, 0.f, 0.f, 0.f};
    if (any) {
        // Branch-free exact mask: out-of-cone -> negative -> 0; tt==0 or
        // r>1 -> NaN -> fmaxf scrubs to 0 (== jnp.nan_to_num(maximum(...))).
#pragma unroll
        for (int j = 0; j < 4; j++) {
            float a0  = a0b + (float)j;
            float dot = fmaf(a0, gx, a1gy);
            float tt  = fmaf(a0, a0, a1sq) * rn2;
            float r   = dot * rsqrtf(tt);
            m[j] = fmaxf(fmaf(-angscale, acosf(r), 1.0f), 0.0f);
        }
    }

    float o0[4], o1[4], o2[4];
#pragma unroll
    for (int j = 0; j < 4; j++) {
        float d = dv[j];
        float e = fabsf(d - pd);             // |d - point_depth|
        float v = d * m[j];
        o0[j] = (e <= cf1) ? v : 0.f;
        o1[j] = (e <= cf2) ? v : 0.f;
        o2[j] = (e <= cf3) ? v : 0.f;
    }

    float* op0 = out + (size_t)b * 3 * HWP + pix;
    *reinterpret_cast<float4*>(op0)           = make_float4(o0[0], o0[1], o0[2], o0[3]);
    *reinterpret_cast<float4*>(op0 + HWP)     = make_float4(o1[0], o1[1], o1[2], o1[3]);
    *reinterpret_cast<float4*>(op0 + 2 * HWP) = make_float4(o2[0], o2[1], o2[2], o2[3]);
}

extern "C" void kernel_launch(void* const* d_in, const int* in_sizes, int n_in,
                              void* d_out, int out_size) {
    const float* depth = (const float*)d_in[0];
    const float* obj   = (const float*)d_in[1];
    const float* gaze  = (const float*)d_in[2];
    const long long* hp = (const long long*)d_in[3];
    float* out = (float*)d_out;

    reduce_kernel<<<dim3(RBLK, BB), 256>>>(depth, obj);
    main_kernel<<<BB * 49, 256>>>(depth, obj, gaze, hp, out);
}